// round 4
// baseline (speedup 1.0000x reference)
#include <cuda_runtime.h>
#include <cstdint>

constexpr int B = 64;
constexpr int T = 1024;
constexpr int V = 512;
constexpr int L = 128;
constexpr int SP  = 288;   // padded per-(b,t) state stride in E (multiple of 32)
constexpr int D   = 6;     // emit LDG register pipeline depth
constexpr int TCH = 16;    // kernel-1 time chunk per CTA

#define NEG2   (-1.44269504e30f)     // -1e30 in log2 domain
#define LN2    0.6931471805599453f
#define LOG2E  1.4426950408889634f
#define NANPAT 0x7FC00000u

__device__ float Eall[(size_t)B * T * SP];   // ~75.5 MB scratch (static, no alloc)
__device__ float g_loss[B];
__device__ int   g_ctr = 0;

__device__ __forceinline__ float ex2f(float x) {
    float y; asm("ex2.approx.f32 %0, %1;" : "=f"(y) : "f"(x)); return y;
}
__device__ __forceinline__ float lg2f(float x) {
    float y; asm("lg2.approx.f32 %0, %1;" : "=f"(y) : "f"(x)); return y;
}
__device__ __forceinline__ float lse3(float a, float b, float c) {
    const float m = fmaxf(a, fmaxf(b, c));
    return m + lg2f(ex2f(a - m) + ex2f(b - m) + ex2f(c - m));
}
__device__ __forceinline__ float lse2(float a, float b) {
    const float m = fmaxf(a, b);
    return m + lg2f(ex2f(a - m) + ex2f(b - m));
}

// ---------------- Kernel 1: emit gather  E[b][t][s] = log2e * outputs[b,t,ext[s]] ----
__global__ __launch_bounds__(288)
void emit_gather(const float* __restrict__ outputs, const int* __restrict__ labels) {
    const int nchunks = T / TCH;
    const int b  = blockIdx.x / nchunks;
    const int t0 = (blockIdx.x % nchunks) * TCH;
    const int tid = threadIdx.x;

    int col = 0;
    if ((tid & 1) && tid < 257) col = __ldg(labels + b * L + ((tid - 1) >> 1));

    if (tid < 257) {
        const float* src = outputs + ((size_t)b * T + t0) * V + col;
        float*       dst = Eall    + ((size_t)b * T + t0) * SP + tid;
        #pragma unroll 4
        for (int k = 0; k < TCH; ++k)
            dst[(size_t)k * SP] = __ldg(src + (size_t)k * V) * LOG2E;
    }
}

// ---------------- Kernel 2: skewed-warp alpha recursion (no block barrier in loop) ---
__global__ __launch_bounds__(128, 1)
void ctc_rec(const int* __restrict__ labels,
             const int* __restrict__ output_lengths,
             const int* __restrict__ label_lengths,
             float* __restrict__ out) {
    __shared__ __align__(16) float2 ring[3][T];   // 24 KB boundary mailboxes
    __shared__ float2 dummy;                      // constant NEG source for warp 0
    __shared__ float2 dump;                       // write sink for warp 3
    __shared__ float  fin[2];

    const int b    = blockIdx.x;
    const int tid  = threadIdx.x;
    const int lane = tid & 31;
    const int w    = tid >> 5;

    // init ring sentinels (NaN = not yet written)
    {
        float4* r4 = (float4*)&ring[0][0];
        const float nf = __uint_as_float(NANPAT);
        const float4 nv = make_float4(nf, nf, nf, nf);
        for (int i = tid; i < 3 * T / 2; i += 128) r4[i] = nv;
        if (tid == 0) dummy = make_float2(NEG2, NEG2);
    }

    const int olen = output_lengths[b];
    const int llen = label_lengths[b];
    const int tcap = olen - 1;
    const int s0g  = 2 * llen - 1;
    const int s1g  = 2 * llen;

    const int sA = w * 64 + lane;     // chain A state
    const int sB = sA + 32;           // chain B state (tid 127 also owns state 256)

    const int* lb = labels + b * L;
    bool skipA = false, skipB = false;
    if (lane & 1) {
        const int liA = (sA - 1) >> 1;
        const int cA  = __ldg(lb + liA);
        skipA = (liA > 0) && (cA != __ldg(lb + liA - 1));
        const int liB = (sB - 1) >> 1;
        const int cB  = __ldg(lb + liB);
        skipB = (cB != __ldg(lb + liB - 1));
    }
    const bool A0 = (sA == s0g), A1 = (sA == s1g);
    const bool B0 = (sB == s0g), B1 = (sB == s1g);
    const bool C1 = (tid == 127) && (s1g == 256);

    const float* EA = Eall + (size_t)b * T * SP + sA;
    const float* EB = EA + 32;

    float eA[D], eB[D];
    #pragma unroll
    for (int k = 0; k < D; ++k) {
        eA[k] = __ldg(EA + (size_t)k * SP);
        eB[k] = __ldg(EB + (size_t)k * SP);
    }

    uint32_t rdAddr = (uint32_t)__cvta_generic_to_shared(
                          (w == 0) ? &dummy : &ring[w - 1][0]);
    const uint32_t rdStep = (w == 0) ? 0u : (uint32_t)sizeof(float2);
    uint32_t wrAddr = (uint32_t)__cvta_generic_to_shared(
                          (w < 3) ? &ring[w][0] : &dump);
    const uint32_t wrStep = (w < 3) ? (uint32_t)sizeof(float2) : 0u;

    __syncthreads();   // ring init + dummy visible; last block barrier until the end

    // ---- peeled t = 0 ----
    float vA = (sA <= 1) ? eA[0] : NEG2;
    float vB = NEG2;
    float vC = NEG2;
    float cap0 = NEG2, cap1 = NEG2;
    {
        const bool pc = (tcap == 0);
        cap0 = (pc && A0) ? vA : cap0;
        cap1 = (pc && A1) ? vA : cap1;
    }
    #pragma unroll
    for (int k = 0; k < D - 1; ++k) { eA[k] = eA[k + 1]; eB[k] = eB[k + 1]; }
    {
        const int tl = (D < T) ? D : (T - 1);
        eA[D - 1] = __ldg(EA + (size_t)tl * SP);
        eB[D - 1] = __ldg(EB + (size_t)tl * SP);
    }
    {   // publish step-0 boundary
        const float b30n = __shfl_sync(0xffffffffu, vB, 30);
        if (lane == 31)
            asm volatile("st.volatile.shared.v2.f32 [%0], {%1,%2};"
                         :: "r"(wrAddr), "f"(b30n), "f"(vB) : "memory");
        wrAddr += wrStep;
    }
    // prefetch boundary for t = 1
    float2 bd;
    do {
        asm volatile("ld.volatile.shared.v2.f32 {%0,%1}, [%2];"
                     : "=f"(bd.x), "=f"(bd.y) : "r"(rdAddr));
    } while (__float_as_uint(bd.y) == NANPAT);
    rdAddr += rdStep;

    // ---- main recursion ----
    for (int t = 1; t < T; ++t) {
        const float eAc = eA[0], eBc = eB[0];

        // old-value broadcasts (before updates)
        const float a31 = __shfl_sync(0xffffffffu, vA, 31);
        const float a30 = __shfl_sync(0xffffffffu, vA, 30);
        const float eC  = __shfl_sync(0xffffffffu, eBc, 30);  // blank emit (s=254)

        // chain C: state 256 (meaningful on tid 127 only)
        vC = lse2(vC, vB) + eC;

        float p1A = __shfl_up_sync(0xffffffffu, vA, 1);
        float p2A = __shfl_up_sync(0xffffffffu, vA, 2);
        p1A = (lane == 0) ? bd.y : p1A;
        p2A = (lane == 0) ? bd.x : ((lane == 1) ? bd.y : p2A);
        p2A = skipA ? p2A : NEG2;

        float p1B = __shfl_up_sync(0xffffffffu, vB, 1);
        float p2B = __shfl_up_sync(0xffffffffu, vB, 2);
        p1B = (lane == 0) ? a31 : p1B;
        p2B = (lane == 0) ? a30 : ((lane == 1) ? a31 : p2B);
        p2B = skipB ? p2B : NEG2;

        vA = lse3(vA, p1A, p2A) + eAc;
        vB = lse3(vB, p1B, p2B) + eBc;

        const bool pc = (t == tcap);
        cap0 = (pc && A0) ? vA : cap0;
        cap0 = (pc && B0) ? vB : cap0;
        cap1 = (pc && A1) ? vA : cap1;
        cap1 = (pc && B1) ? vB : cap1;
        cap1 = (pc && C1) ? vC : cap1;

        // publish this step's top boundary
        const float b30n = __shfl_sync(0xffffffffu, vB, 30);
        if (lane == 31)
            asm volatile("st.volatile.shared.v2.f32 [%0], {%1,%2};"
                         :: "r"(wrAddr), "f"(b30n), "f"(vB) : "memory");
        wrAddr += wrStep;

        // emit pipeline shift + refill
        #pragma unroll
        for (int k = 0; k < D - 1; ++k) { eA[k] = eA[k + 1]; eB[k] = eB[k + 1]; }
        int tl = t + D; tl = (tl < T) ? tl : (T - 1);
        eA[D - 1] = __ldg(EA + (size_t)tl * SP);
        eB[D - 1] = __ldg(EB + (size_t)tl * SP);

        // prefetch boundary for t + 1 (usually already written: leader is ahead)
        do {
            asm volatile("ld.volatile.shared.v2.f32 {%0,%1}, [%2];"
                         : "=f"(bd.x), "=f"(bd.y) : "r"(rdAddr));
        } while (__float_as_uint(bd.y) == NANPAT);
        rdAddr += rdStep;
    }

    // ---- finish ----
    __syncthreads();
    if (A0 || B0) fin[0] = cap0;
    if (A1 || B1 || C1) fin[1] = cap1;
    __syncthreads();

    if (tid == 0) {
        const float ll = lse2(fin[0], fin[1]) * LN2;
        g_loss[b] = -ll / (float)llen;
        __threadfence();
        const int old = atomicAdd(&g_ctr, 1);
        if (old == B - 1) {
            __threadfence();
            float s = 0.0f;
            #pragma unroll 8
            for (int i = 0; i < B; ++i) s += g_loss[i];
            *out = s * (1.0f / (float)B);
            g_ctr = 0;   // reset for next graph replay
        }
    }
}

extern "C" void kernel_launch(void* const* d_in, const int* in_sizes, int n_in,
                              void* d_out, int out_size) {
    const float* outputs        = (const float*)d_in[0];
    const int*   labels         = (const int*)d_in[1];
    const int*   output_lengths = (const int*)d_in[2];
    const int*   label_lengths  = (const int*)d_in[3];
    float* out = (float*)d_out;

    emit_gather<<<B * (T / TCH), 288>>>(outputs, labels);
    ctc_rec<<<B, 128>>>(labels, output_lengths, label_lengths, out);
}

// round 5
// speedup vs baseline: 3.2903x; 3.2903x over previous
#include <cuda_runtime.h>
#include <cstdint>

constexpr int B = 64;
constexpr int T = 1024;
constexpr int V = 512;
constexpr int L = 128;
constexpr int NSTAGE = 6;        // cp.async row ring depth
constexpr int THREADS = 128;     // 4 warps; lane i of warp w owns states 64w+2i, 64w+2i+1

#define NEG2   (-1.44269504e30f)     // -1e30 in log2 domain
#define LOG2E  1.4426950408889634f
#define LN2    0.6931471805599453f

__device__ float g_loss[B];
__device__ int   g_ctr = 0;

__device__ __forceinline__ float ex2f(float x) {
    float y; asm("ex2.approx.f32 %0, %1;" : "=f"(y) : "f"(x)); return y;
}
__device__ __forceinline__ float lg2f(float x) {
    float y; asm("lg2.approx.f32 %0, %1;" : "=f"(y) : "f"(x)); return y;
}
__device__ __forceinline__ float lse2(float a, float b) {
    const float m = fmaxf(a, b);
    return m + lg2f(ex2f(a - m) + ex2f(b - m));
}
__device__ __forceinline__ float lse3(float a, float b, float c) {
    const float m = fmaxf(a, fmaxf(b, c));
    return m + lg2f(ex2f(a - m) + ex2f(b - m) + ex2f(c - m));
}

__device__ __forceinline__ void cp_async16(void* sptr, const void* gptr) {
    uint32_t sa = (uint32_t)__cvta_generic_to_shared(sptr);
    asm volatile("cp.async.cg.shared.global [%0], [%1], 16;\n" ::"r"(sa), "l"(gptr));
}
__device__ __forceinline__ void cp_commit() {
    asm volatile("cp.async.commit_group;\n");
}
template <int N>
__device__ __forceinline__ void cp_wait() {
    asm volatile("cp.async.wait_group %0;\n" ::"n"(N));
}

__global__ __launch_bounds__(THREADS, 1)
void ctc_fused_kernel(const float* __restrict__ outputs,
                      const int*   __restrict__ labels,
                      const int*   __restrict__ output_lengths,
                      const int*   __restrict__ label_lengths,
                      float* __restrict__ out) {
    __shared__ __align__(16) float rowbuf[NSTAGE][V];   // 12 KB
    __shared__ float bnd[2][5];    // [buf][w] = alpha[64w+63]; [buf][4] = NEG const
    __shared__ float fin[2];

    const int b    = blockIdx.x;
    const int tid  = threadIdx.x;
    const int lane = tid & 31;
    const int w    = tid >> 5;

    const int olen = output_lengths[b];
    const int llen = label_lengths[b];
    const int tcap = olen - 1;
    const int s0g  = 2 * llen - 1;       // odd  -> lives on a B chain
    const int s1g  = 2 * llen;           // even -> lives on an A chain (or state 256)

    // states owned by this thread
    const int sA = (w << 6) + (lane << 1);   // even state
    const int sB = sA + 1;                   // odd  state; label index = tid

    // static per-thread data
    const int* lb = labels + b * L;
    const int  colB  = __ldg(lb + tid);                       // tid in [0,128) == li
    const bool skipB = (tid > 0) && (colB != __ldg(lb + tid - 1));

    const bool capA1 = (sA == s1g);
    const bool capB0 = (sB == s0g);
    const bool capC1 = (tid == 127) && (s1g == 256);
    const int  rdi   = (w == 0) ? 4 : (w - 1);    // boundary source slot

    // ---- cp.async prologue: rows 0..NSTAGE-2 ----
    const float* gb = outputs + (size_t)b * T * V;
    const int le = tid * 4;                        // 16B/thread covers the 2KB row
    #pragma unroll
    for (int k = 0; k < NSTAGE - 1; ++k) {
        cp_async16(&rowbuf[k][le], gb + (size_t)k * V + le);
        cp_commit();
    }

    if (tid < 2) bnd[tid][4] = NEG2;

    cp_wait<3>();        // rows 0 and 1 landed
    __syncthreads();

    // ---- peeled t = 0 ----
    float A, Bv, C = NEG2;
    float cap0 = NEG2, cap1 = NEG2;
    {
        const float eA0 = rowbuf[0][0]    * LOG2E;
        const float eB0 = rowbuf[0][colB] * LOG2E;
        A  = (sA == 0) ? eA0 : NEG2;
        Bv = (sB == 1) ? eB0 : NEG2;
        const bool pc = (tcap == 0);
        cap1 = (pc && capA1) ? A  : cap1;
        cap0 = (pc && capB0) ? Bv : cap0;
        if (lane == 31) bnd[1][w] = Bv;
    }
    // prefetch emits for t = 1 (row 1 already resident)
    float eAc = rowbuf[1][0]    * LOG2E;
    float eBc = rowbuf[1][colB] * LOG2E;
    // issue row NSTAGE-1
    cp_async16(&rowbuf[NSTAGE - 1][le], gb + (size_t)(NSTAGE - 1) * V + le);
    cp_commit();

    int nsI = 2;   // stage of row t+1 (for emit prefetch), t starts at 1
    int wsI = 0;   // stage to receive row t+NSTAGE-1

    // ---- main recursion ----
    for (int t = 1; t < T; ++t) {
        cp_wait<3>();          // rows <= t+1 landed
        __syncthreads();       // bnd[t&1] publishes visible

        // boundary + neighbor (single shfl serves both chains)
        const float bd  = bnd[t & 1][rdi];
        float Bm1 = __shfl_up_sync(0xffffffffu, Bv, 1);
        Bm1 = (lane == 0) ? bd : Bm1;

        // state 256 chain (meaningful on tid 127 only; uses OLD Bv = alpha[255])
        const float nC = lse2(C, Bv) + eAc;
        // even state: lse2(own, odd-below)
        const float nA = lse2(A, Bm1) + eAc;
        // odd state: lse3(own, even-same-lane, skip? odd-below-below)
        const float p2 = skipB ? Bm1 : NEG2;
        const float nB = lse3(Bv, A, p2) + eBc;
        A = nA; Bv = nB; C = nC;

        // branch-free captures
        const bool pc = (t == tcap);
        cap1 = (pc && capA1) ? A  : cap1;
        cap0 = (pc && capB0) ? Bv : cap0;
        cap1 = (pc && capC1) ? C  : cap1;

        // publish this step's warp-top boundary (predicated single STS)
        if (lane == 31) bnd[(t + 1) & 1][w] = Bv;

        // off-chain: prefetch emits for t+1
        const float* nrow = rowbuf[nsI];
        eAc = nrow[0]    * LOG2E;
        eBc = nrow[colB] * LOG2E;

        // off-chain: issue row t+NSTAGE-1 (clamped to keep group count uniform)
        int tp = t + NSTAGE - 1; tp = (tp < T) ? tp : (T - 1);
        cp_async16(&rowbuf[wsI][le], gb + (size_t)tp * V + le);
        cp_commit();

        nsI = (nsI + 1 == NSTAGE) ? 0 : nsI + 1;
        wsI = (wsI + 1 == NSTAGE) ? 0 : wsI + 1;
    }

    // ---- finish ----
    __syncthreads();
    if (capB0) fin[0] = cap0;
    if (capA1 || capC1) fin[1] = cap1;
    __syncthreads();

    if (tid == 0) {
        const float ll = lse2(fin[0], fin[1]) * LN2;
        g_loss[b] = -ll / (float)llen;
        __threadfence();
        const int old = atomicAdd(&g_ctr, 1);
        if (old == B - 1) {
            __threadfence();
            float s = 0.0f;
            #pragma unroll 8
            for (int i = 0; i < B; ++i) s += g_loss[i];
            *out = s * (1.0f / (float)B);
            g_ctr = 0;   // reset for next graph replay
        }
    }
}

extern "C" void kernel_launch(void* const* d_in, const int* in_sizes, int n_in,
                              void* d_out, int out_size) {
    const float* outputs        = (const float*)d_in[0];
    const int*   labels         = (const int*)d_in[1];
    const int*   output_lengths = (const int*)d_in[2];
    const int*   label_lengths  = (const int*)d_in[3];
    float* out = (float*)d_out;

    ctc_fused_kernel<<<B, THREADS>>>(outputs, labels, output_lengths,
                                     label_lengths, out);
}